// round 9
// baseline (speedup 1.0000x reference)
#include <cuda_runtime.h>
#include <math.h>

#define BB 2
#define SS 2048
#define EE 4096
#define HQN 32
#define HKVN 8
#define DD 128
#define NROWS (BB*SS)      // 4096
#define WIN 1024
#define TQ 64
#define TK 64

// ---------------- scratch ----------------
__device__ float g_q[(size_t)NROWS * HQN * DD];
__device__ float g_k[(size_t)NROWS * HKVN * DD];
__device__ float g_v[(size_t)NROWS * HKVN * DD];
__device__ float g_attn[(size_t)NROWS * HQN * DD];

// ---------------- SGEMM: C[MxN] = A[MxK] * B[KxN], row-major ----------------
__global__ __launch_bounds__(256) void sgemm_kernel(
    const float* __restrict__ A, const float* __restrict__ B, float* __restrict__ C,
    int M, int N, int K)
{
    __shared__ float As[8][128];
    __shared__ float Bs[8][128];

    const int tid = threadIdx.x;
    const int tx = tid & 15;
    const int ty = tid >> 4;

    const float* Ap = A + (size_t)blockIdx.y * 128 * K;
    const float* Bp = B + (size_t)blockIdx.x * 128;

    const int a_row = tid >> 1;
    const int a_col = (tid & 1) * 4;
    const int b_row = tid >> 5;
    const int b_col = (tid & 31) * 4;

    float acc[8][8];
#pragma unroll
    for (int i = 0; i < 8; i++)
#pragma unroll
        for (int j = 0; j < 8; j++) acc[i][j] = 0.0f;

    for (int k0 = 0; k0 < K; k0 += 8) {
        float4 av = *(const float4*)(Ap + (size_t)a_row * K + k0 + a_col);
        float4 bv = *(const float4*)(Bp + (size_t)(k0 + b_row) * N + b_col);
        As[a_col + 0][a_row] = av.x;
        As[a_col + 1][a_row] = av.y;
        As[a_col + 2][a_row] = av.z;
        As[a_col + 3][a_row] = av.w;
        *(float4*)&Bs[b_row][b_col] = bv;
        __syncthreads();

#pragma unroll
        for (int kk = 0; kk < 8; kk++) {
            float af[8], bf[8];
#pragma unroll
            for (int i = 0; i < 8; i++) af[i] = As[kk][ty * 8 + i];
#pragma unroll
            for (int j = 0; j < 8; j++) bf[j] = Bs[kk][tx * 8 + j];
#pragma unroll
            for (int i = 0; i < 8; i++)
#pragma unroll
                for (int j = 0; j < 8; j++) acc[i][j] += af[i] * bf[j];
        }
        __syncthreads();
    }

    float* Cp = C + ((size_t)blockIdx.y * 128 + ty * 8) * N + (size_t)blockIdx.x * 128 + tx * 8;
#pragma unroll
    for (int i = 0; i < 8; i++) {
        *(float4*)(Cp + (size_t)i * N)     = make_float4(acc[i][0], acc[i][1], acc[i][2], acc[i][3]);
        *(float4*)(Cp + (size_t)i * N + 4) = make_float4(acc[i][4], acc[i][5], acc[i][6], acc[i][7]);
    }
}

// ---------------- l2norm + RoPE (half-split) + q scaling.  SINCOSF FIXED. ----------------
__global__ __launch_bounds__(128) void norm_rope_kernel(float* __restrict__ data, int H, int isQ)
{
    const int idx = blockIdx.x;        // row*H + h
    const int s = (idx / H) % SS;
    float* ptr = data + (size_t)idx * DD;
    const int d = threadIdx.x;

    __shared__ float s2[DD];
    __shared__ float sh[DD];

    float v = ptr[d];
    s2[d] = v * v;
    __syncthreads();
#pragma unroll
    for (int st = 64; st > 0; st >>= 1) {
        if (d < st) s2[d] += s2[d + st];
        __syncthreads();
    }
    float inv = rsqrtf(s2[0] * (1.0f / DD) + 1e-6f);
    sh[d] = v * inv;
    __syncthreads();

    const int i = d & 63;
    float freq = (float)exp(-(double)i * (9.210340371976184 / 64.0));  // 10000^(-i/64)
    float angle = (float)s * freq;
    float sn, c;
    sincosf(angle, &sn, &c);           // sin FIRST, cos SECOND (this was the bug)
    float x1 = sh[i];
    float x2 = sh[i + 64];
    float out = (d < 64) ? (x1 * c - x2 * sn) : (x2 * c + x1 * sn);

    if (isQ) {
        float asc = logf(floorf(((float)s + 1.0f) / 8192.0f) + 1.0f) * 0.1f + 1.0f;
        out *= 0.08838834764831845f * asc;   // 128^{-1/2} * attn_scale(=1)
    }
    ptr[d] = out;
}

// ---------------- flash attention (windowed causal, softcap) ----------------
__global__ __launch_bounds__(256) void attn_kernel()
{
    extern __shared__ float sm[];
    float* sQ = sm;                    // 64 x 128
    float* sK = sQ + 64 * 128;         // 64 x 129 (padded)
    float* sV = sK + 64 * 129;         // 64 x 128
    float* sL = sV + 64 * 128;         // 64 x 65
    float* sM = sL + 64 * 65;          // 64
    float* sSum = sM + 64;             // 64
    float* sAlpha = sSum + 64;         // 64

    const int b  = blockIdx.z;
    const int h  = blockIdx.y;
    const int q0 = blockIdx.x * TQ;
    const int hk = h / (HQN / HKVN);

    const int tid = threadIdx.x;
    const int tx = tid & 15;
    const int ty = tid >> 4;

    for (int idx = tid; idx < 64 * 32; idx += 256) {
        int r  = idx >> 5;
        int dc = (idx & 31) << 2;
        float4 qv = *(const float4*)&g_q[(((size_t)(b * SS + q0 + r)) * HQN + h) * DD + dc];
        *(float4*)&sQ[r * 128 + dc] = qv;
    }
    if (tid < 64) { sM[tid] = -30000.0f; sSum[tid] = 0.0f; }

    float o[4][8];
#pragma unroll
    for (int r = 0; r < 4; r++)
#pragma unroll
        for (int c = 0; c < 8; c++) o[r][c] = 0.0f;

    int jlo = q0 - (WIN - 1); if (jlo < 0) jlo = 0;
    int jt0 = (jlo / TK) * TK;

    for (int jt = jt0; jt <= q0; jt += TK) {
        __syncthreads();

        for (int idx = tid; idx < 64 * 32; idx += 256) {
            int r  = idx >> 5;
            int dc = (idx & 31) << 2;
            size_t gbase = (((size_t)(b * SS + jt + r)) * HKVN + hk) * DD + dc;
            float4 kv = *(const float4*)&g_k[gbase];
            sK[r * 129 + dc + 0] = kv.x;
            sK[r * 129 + dc + 1] = kv.y;
            sK[r * 129 + dc + 2] = kv.z;
            sK[r * 129 + dc + 3] = kv.w;
            float4 vv = *(const float4*)&g_v[gbase];
            *(float4*)&sV[r * 128 + dc] = vv;
        }
        __syncthreads();

        float acc[4][4];
#pragma unroll
        for (int r = 0; r < 4; r++)
#pragma unroll
            for (int c = 0; c < 4; c++) acc[r][c] = 0.0f;

#pragma unroll 4
        for (int d = 0; d < DD; d++) {
            float af[4], bf[4];
#pragma unroll
            for (int r = 0; r < 4; r++) af[r] = sQ[(ty * 4 + r) * 128 + d];
#pragma unroll
            for (int c = 0; c < 4; c++) bf[c] = sK[(tx * 4 + c) * 129 + d];
#pragma unroll
            for (int r = 0; r < 4; r++)
#pragma unroll
                for (int c = 0; c < 4; c++) acc[r][c] += af[r] * bf[c];
        }

#pragma unroll
        for (int r = 0; r < 4; r++) {
            int i = q0 + ty * 4 + r;
#pragma unroll
            for (int c = 0; c < 4; c++) {
                int j = jt + tx * 4 + c;
                float lg = 50.0f * tanhf(acc[r][c] * 0.02f);
                bool valid = (j <= i) && (i - j < WIN);
                sL[(ty * 4 + r) * 65 + tx * 4 + c] = valid ? lg : -30000.0f;
            }
        }
        __syncthreads();

        if (tid < 64) {
            float tm = -30000.0f;
            for (int j = 0; j < TK; j++) tm = fmaxf(tm, sL[tid * 65 + j]);
            float mo = sM[tid];
            float mn = fmaxf(mo, tm);
            float alpha = __expf(mo - mn);
            float rs = 0.0f;
            for (int j = 0; j < TK; j++) {
                float lv = sL[tid * 65 + j];
                float p = (lv > -20000.0f) ? __expf(lv - mn) : 0.0f;
                sL[tid * 65 + j] = p;
                rs += p;
            }
            sSum[tid] = sSum[tid] * alpha + rs;
            sM[tid] = mn;
            sAlpha[tid] = alpha;
        }
        __syncthreads();

#pragma unroll
        for (int r = 0; r < 4; r++) {
            float a = sAlpha[ty * 4 + r];
#pragma unroll
            for (int c = 0; c < 8; c++) o[r][c] *= a;
        }
#pragma unroll 2
        for (int j = 0; j < TK; j++) {
            float4 v0 = *(const float4*)&sV[j * 128 + tx * 8];
            float4 v1 = *(const float4*)&sV[j * 128 + tx * 8 + 4];
#pragma unroll
            for (int r = 0; r < 4; r++) {
                float p = sL[(ty * 4 + r) * 65 + j];
                o[r][0] += p * v0.x; o[r][1] += p * v0.y;
                o[r][2] += p * v0.z; o[r][3] += p * v0.w;
                o[r][4] += p * v1.x; o[r][5] += p * v1.y;
                o[r][6] += p * v1.z; o[r][7] += p * v1.w;
            }
        }
    }

#pragma unroll
    for (int r = 0; r < 4; r++) {
        float inv = 1.0f / sSum[ty * 4 + r];
        size_t base = (((size_t)(b * SS + q0 + ty * 4 + r)) * HQN + h) * DD + tx * 8;
        *(float4*)&g_attn[base]     = make_float4(o[r][0] * inv, o[r][1] * inv, o[r][2] * inv, o[r][3] * inv);
        *(float4*)&g_attn[base + 4] = make_float4(o[r][4] * inv, o[r][5] * inv, o[r][6] * inv, o[r][7] * inv);
    }
}

// ---------------- launch ----------------
extern "C" void kernel_launch(void* const* d_in, const int* in_sizes, int n_in,
                              void* d_out, int out_size)
{
    const float* x  = (const float*)d_in[0];
    const float* Wq = (const float*)d_in[1];
    const float* Wk = (const float*)d_in[2];
    const float* Wv = (const float*)d_in[3];
    const float* Wo = (const float*)d_in[4];
    float* out = (float*)d_out;

    float *q, *k, *v, *attn;
    cudaGetSymbolAddress((void**)&q,    g_q);
    cudaGetSymbolAddress((void**)&k,    g_k);
    cudaGetSymbolAddress((void**)&v,    g_v);
    cudaGetSymbolAddress((void**)&attn, g_attn);

    // QKV projections
    sgemm_kernel<<<dim3(HQN * DD / 128, NROWS / 128), 256>>>(x, Wq, q, NROWS, HQN * DD, EE);
    sgemm_kernel<<<dim3(HKVN * DD / 128, NROWS / 128), 256>>>(x, Wk, k, NROWS, HKVN * DD, EE);
    sgemm_kernel<<<dim3(HKVN * DD / 128, NROWS / 128), 256>>>(x, Wv, v, NROWS, HKVN * DD, EE);

    // l2norm + rope (+ q scales)
    norm_rope_kernel<<<NROWS * HQN, 128>>>(q, HQN, 1);
    norm_rope_kernel<<<NROWS * HKVN, 128>>>(k, HKVN, 0);

    // attention
    const int att_smem = (64 * 128 + 64 * 129 + 64 * 128 + 64 * 65 + 3 * 64) * (int)sizeof(float);
    cudaFuncSetAttribute(attn_kernel, cudaFuncAttributeMaxDynamicSharedMemorySize, att_smem);
    attn_kernel<<<dim3(SS / TQ, HQN, BB), 256, att_smem>>>();

    // output projection
    sgemm_kernel<<<dim3(EE / 128, NROWS / 128), 256>>>(attn, Wo, out, NROWS, EE, HQN * DD);
}

// round 10
// speedup vs baseline: 1.8007x; 1.8007x over previous
#include <cuda_runtime.h>
#include <math.h>
#include <stdint.h>

#define BB 2
#define SS 2048
#define EE 4096
#define HQN 32
#define HKVN 8
#define DD 128
#define NROWS (BB*SS)      // 4096
#define WIN 1024
#define TQ 64
#define TK 64

// ---------------- scratch ----------------
__device__ float g_q[(size_t)NROWS * HQN * DD];
__device__ float g_k[(size_t)NROWS * HKVN * DD];
__device__ float g_v[(size_t)NROWS * HKVN * DD];
__device__ float g_attn[(size_t)NROWS * HQN * DD];

// ---------------- helpers ----------------
__device__ __forceinline__ uint32_t f2tf32(float f) {
    uint32_t u;
    asm("cvt.rna.tf32.f32 %0, %1;" : "=r"(u) : "f"(f));
    return u;
}

__device__ __forceinline__ void mma_tf32(float c[4], const uint32_t a[4], const uint32_t b[2]) {
    asm volatile(
        "mma.sync.aligned.m16n8k8.row.col.f32.tf32.tf32.f32 "
        "{%0,%1,%2,%3}, {%4,%5,%6,%7}, {%8,%9}, {%0,%1,%2,%3};\n"
        : "+f"(c[0]), "+f"(c[1]), "+f"(c[2]), "+f"(c[3])
        : "r"(a[0]), "r"(a[1]), "r"(a[2]), "r"(a[3]), "r"(b[0]), "r"(b[1]));
}

// ---------------- TF32 GEMM: C[MxN] = A[MxK] * B[KxN], row-major, M%128==0, N%128==0, K%16==0 ----
// CTA: 128x128 tile, 256 threads (8 warps), warp tile 64x32, mma m16n8k8.
#define AS_STRIDE 136   // floats; 136 % 32 == 8 -> conflict-free k-group banks
__global__ __launch_bounds__(256) void gemm_tf32_kernel(
    const float* __restrict__ A, const float* __restrict__ B, float* __restrict__ C,
    int M, int N, int K)
{
    __shared__ uint32_t As[16][AS_STRIDE];   // [k][m] (transposed)
    __shared__ uint32_t Bs[16][AS_STRIDE];   // [k][n]

    const int tid  = threadIdx.x;
    const int warp = tid >> 5;
    const int lane = tid & 31;
    const int l4   = lane & 3;    // k sub-index
    const int l28  = lane >> 2;   // 0..7

    const int m0 = (warp >> 2) * 64;   // warp row offset in tile
    const int n0 = (warp & 3) * 32;    // warp col offset in tile

    const int row0 = blockIdx.y * 128;
    const int col0 = blockIdx.x * 128;

    float cacc[4][4][4];
#pragma unroll
    for (int mt = 0; mt < 4; mt++)
#pragma unroll
        for (int nt = 0; nt < 4; nt++)
#pragma unroll
            for (int r = 0; r < 4; r++) cacc[mt][nt][r] = 0.0f;

    for (int k0 = 0; k0 < K; k0 += 16) {
        // load A tile 128x16 (transpose into As[k][m]) — 512 float4, 2 per thread
#pragma unroll
        for (int i = 0; i < 2; i++) {
            int idx = tid + i * 256;
            int r  = idx >> 2;
            int c4 = (idx & 3) << 2;
            float4 av = *(const float4*)(A + (size_t)(row0 + r) * K + k0 + c4);
            As[c4 + 0][r] = f2tf32(av.x);
            As[c4 + 1][r] = f2tf32(av.y);
            As[c4 + 2][r] = f2tf32(av.z);
            As[c4 + 3][r] = f2tf32(av.w);
        }
        // load B tile 16x128 into Bs[k][n]
#pragma unroll
        for (int i = 0; i < 2; i++) {
            int idx = tid + i * 256;
            int r = idx >> 5;
            int c = (idx & 31) << 2;
            float4 bv = *(const float4*)(B + (size_t)(k0 + r) * N + col0 + c);
            Bs[r][c + 0] = f2tf32(bv.x);
            Bs[r][c + 1] = f2tf32(bv.y);
            Bs[r][c + 2] = f2tf32(bv.z);
            Bs[r][c + 3] = f2tf32(bv.w);
        }
        __syncthreads();

#pragma unroll
        for (int ks = 0; ks < 16; ks += 8) {
            uint32_t bf[4][2];
#pragma unroll
            for (int nt = 0; nt < 4; nt++) {
                int n = n0 + nt * 8 + l28;
                bf[nt][0] = Bs[ks + l4][n];
                bf[nt][1] = Bs[ks + 4 + l4][n];
            }
            uint32_t af[4];
#pragma unroll
            for (int mt = 0; mt < 4; mt++) {
                int m = m0 + mt * 16 + l28;
                af[0] = As[ks + l4][m];
                af[1] = As[ks + l4][m + 8];
                af[2] = As[ks + 4 + l4][m];
                af[3] = As[ks + 4 + l4][m + 8];
#pragma unroll
                for (int nt = 0; nt < 4; nt++)
                    mma_tf32(cacc[mt][nt], af, bf[nt]);
            }
        }
        __syncthreads();
    }

    // epilogue
#pragma unroll
    for (int mt = 0; mt < 4; mt++) {
#pragma unroll
        for (int nt = 0; nt < 4; nt++) {
            int row = row0 + m0 + mt * 16 + l28;
            int col = col0 + n0 + nt * 8 + (l4 << 1);
            *(float2*)(C + (size_t)row * N + col)       = make_float2(cacc[mt][nt][0], cacc[mt][nt][1]);
            *(float2*)(C + (size_t)(row + 8) * N + col) = make_float2(cacc[mt][nt][2], cacc[mt][nt][3]);
        }
    }
}

// ---------------- l2norm + RoPE (half-split) + q scaling ----------------
__global__ __launch_bounds__(128) void norm_rope_kernel(float* __restrict__ data, int H, int isQ)
{
    const int idx = blockIdx.x;
    const int s = (idx / H) % SS;
    float* ptr = data + (size_t)idx * DD;
    const int d = threadIdx.x;

    __shared__ float s2[DD];
    __shared__ float sh[DD];

    float v = ptr[d];
    s2[d] = v * v;
    __syncthreads();
#pragma unroll
    for (int st = 64; st > 0; st >>= 1) {
        if (d < st) s2[d] += s2[d + st];
        __syncthreads();
    }
    float inv = rsqrtf(s2[0] * (1.0f / DD) + 1e-6f);
    sh[d] = v * inv;
    __syncthreads();

    const int i = d & 63;
    float freq = (float)exp(-(double)i * (9.210340371976184 / 64.0));
    float angle = (float)s * freq;
    float sn, c;
    sincosf(angle, &sn, &c);
    float x1 = sh[i];
    float x2 = sh[i + 64];
    float out = (d < 64) ? (x1 * c - x2 * sn) : (x2 * c + x1 * sn);

    if (isQ) {
        float asc = logf(floorf(((float)s + 1.0f) / 8192.0f) + 1.0f) * 0.1f + 1.0f;
        out *= 0.08838834764831845f * asc;
    }
    ptr[d] = out;
}

// ---------------- flash attention (windowed causal, softcap) ----------------
__global__ __launch_bounds__(256) void attn_kernel()
{
    extern __shared__ float sm[];
    float* sQ = sm;
    float* sK = sQ + 64 * 128;
    float* sV = sK + 64 * 129;
    float* sL = sV + 64 * 128;
    float* sM = sL + 64 * 65;
    float* sSum = sM + 64;
    float* sAlpha = sSum + 64;

    const int b  = blockIdx.z;
    const int h  = blockIdx.y;
    const int q0 = blockIdx.x * TQ;
    const int hk = h / (HQN / HKVN);

    const int tid = threadIdx.x;
    const int tx = tid & 15;
    const int ty = tid >> 4;

    for (int idx = tid; idx < 64 * 32; idx += 256) {
        int r  = idx >> 5;
        int dc = (idx & 31) << 2;
        float4 qv = *(const float4*)&g_q[(((size_t)(b * SS + q0 + r)) * HQN + h) * DD + dc];
        *(float4*)&sQ[r * 128 + dc] = qv;
    }
    if (tid < 64) { sM[tid] = -30000.0f; sSum[tid] = 0.0f; }

    float o[4][8];
#pragma unroll
    for (int r = 0; r < 4; r++)
#pragma unroll
        for (int c = 0; c < 8; c++) o[r][c] = 0.0f;

    int jlo = q0 - (WIN - 1); if (jlo < 0) jlo = 0;
    int jt0 = (jlo / TK) * TK;

    for (int jt = jt0; jt <= q0; jt += TK) {
        __syncthreads();

        for (int idx = tid; idx < 64 * 32; idx += 256) {
            int r  = idx >> 5;
            int dc = (idx & 31) << 2;
            size_t gbase = (((size_t)(b * SS + jt + r)) * HKVN + hk) * DD + dc;
            float4 kv = *(const float4*)&g_k[gbase];
            sK[r * 129 + dc + 0] = kv.x;
            sK[r * 129 + dc + 1] = kv.y;
            sK[r * 129 + dc + 2] = kv.z;
            sK[r * 129 + dc + 3] = kv.w;
            float4 vv = *(const float4*)&g_v[gbase];
            *(float4*)&sV[r * 128 + dc] = vv;
        }
        __syncthreads();

        float acc[4][4];
#pragma unroll
        for (int r = 0; r < 4; r++)
#pragma unroll
            for (int c = 0; c < 4; c++) acc[r][c] = 0.0f;

#pragma unroll 4
        for (int d = 0; d < DD; d++) {
            float af[4], bf[4];
#pragma unroll
            for (int r = 0; r < 4; r++) af[r] = sQ[(ty * 4 + r) * 128 + d];
#pragma unroll
            for (int c = 0; c < 4; c++) bf[c] = sK[(tx * 4 + c) * 129 + d];
#pragma unroll
            for (int r = 0; r < 4; r++)
#pragma unroll
                for (int c = 0; c < 4; c++) acc[r][c] += af[r] * bf[c];
        }

#pragma unroll
        for (int r = 0; r < 4; r++) {
            int i = q0 + ty * 4 + r;
#pragma unroll
            for (int c = 0; c < 4; c++) {
                int j = jt + tx * 4 + c;
                float lg = 50.0f * tanhf(acc[r][c] * 0.02f);
                bool valid = (j <= i) && (i - j < WIN);
                sL[(ty * 4 + r) * 65 + tx * 4 + c] = valid ? lg : -30000.0f;
            }
        }
        __syncthreads();

        if (tid < 64) {
            float tm = -30000.0f;
            for (int j = 0; j < TK; j++) tm = fmaxf(tm, sL[tid * 65 + j]);
            float mo = sM[tid];
            float mn = fmaxf(mo, tm);
            float alpha = __expf(mo - mn);
            float rs = 0.0f;
            for (int j = 0; j < TK; j++) {
                float lv = sL[tid * 65 + j];
                float p = (lv > -20000.0f) ? __expf(lv - mn) : 0.0f;
                sL[tid * 65 + j] = p;
                rs += p;
            }
            sSum[tid] = sSum[tid] * alpha + rs;
            sM[tid] = mn;
            sAlpha[tid] = alpha;
        }
        __syncthreads();

#pragma unroll
        for (int r = 0; r < 4; r++) {
            float a = sAlpha[ty * 4 + r];
#pragma unroll
            for (int c = 0; c < 8; c++) o[r][c] *= a;
        }
#pragma unroll 2
        for (int j = 0; j < TK; j++) {
            float4 v0 = *(const float4*)&sV[j * 128 + tx * 8];
            float4 v1 = *(const float4*)&sV[j * 128 + tx * 8 + 4];
#pragma unroll
            for (int r = 0; r < 4; r++) {
                float p = sL[(ty * 4 + r) * 65 + j];
                o[r][0] += p * v0.x; o[r][1] += p * v0.y;
                o[r][2] += p * v0.z; o[r][3] += p * v0.w;
                o[r][4] += p * v1.x; o[r][5] += p * v1.y;
                o[r][6] += p * v1.z; o[r][7] += p * v1.w;
            }
        }
    }

#pragma unroll
    for (int r = 0; r < 4; r++) {
        float inv = 1.0f / sSum[ty * 4 + r];
        size_t base = (((size_t)(b * SS + q0 + ty * 4 + r)) * HQN + h) * DD + tx * 8;
        *(float4*)&g_attn[base]     = make_float4(o[r][0] * inv, o[r][1] * inv, o[r][2] * inv, o[r][3] * inv);
        *(float4*)&g_attn[base + 4] = make_float4(o[r][4] * inv, o[r][5] * inv, o[r][6] * inv, o[r][7] * inv);
    }
}

// ---------------- launch ----------------
extern "C" void kernel_launch(void* const* d_in, const int* in_sizes, int n_in,
                              void* d_out, int out_size)
{
    const float* x  = (const float*)d_in[0];
    const float* Wq = (const float*)d_in[1];
    const float* Wk = (const float*)d_in[2];
    const float* Wv = (const float*)d_in[3];
    const float* Wo = (const float*)d_in[4];
    float* out = (float*)d_out;

    float *q, *k, *v, *attn;
    cudaGetSymbolAddress((void**)&q,    g_q);
    cudaGetSymbolAddress((void**)&k,    g_k);
    cudaGetSymbolAddress((void**)&v,    g_v);
    cudaGetSymbolAddress((void**)&attn, g_attn);

    // QKV projections (tf32 tensor cores)
    gemm_tf32_kernel<<<dim3(HQN * DD / 128, NROWS / 128), 256>>>(x, Wq, q, NROWS, HQN * DD, EE);
    gemm_tf32_kernel<<<dim3(HKVN * DD / 128, NROWS / 128), 256>>>(x, Wk, k, NROWS, HKVN * DD, EE);
    gemm_tf32_kernel<<<dim3(HKVN * DD / 128, NROWS / 128), 256>>>(x, Wv, v, NROWS, HKVN * DD, EE);

    // l2norm + rope (+ q scales)
    norm_rope_kernel<<<NROWS * HQN, 128>>>(q, HQN, 1);
    norm_rope_kernel<<<NROWS * HKVN, 128>>>(k, HKVN, 0);

    // attention
    const int att_smem = (64 * 128 + 64 * 129 + 64 * 128 + 64 * 65 + 3 * 64) * (int)sizeof(float);
    cudaFuncSetAttribute(attn_kernel, cudaFuncAttributeMaxDynamicSharedMemorySize, att_smem);
    attn_kernel<<<dim3(SS / TQ, HQN, BB), 256, att_smem>>>();

    // output projection (tf32 tensor cores)
    gemm_tf32_kernel<<<dim3(EE / 128, NROWS / 128), 256>>>(attn, Wo, out, NROWS, EE, HQN * DD);
}

// round 11
// speedup vs baseline: 2.2189x; 1.2323x over previous
#include <cuda_runtime.h>
#include <math.h>
#include <stdint.h>

#define BB 2
#define SS 2048
#define EE 4096
#define HQN 32
#define HKVN 8
#define DD 128
#define NROWS (BB*SS)      // 4096
#define WIN 1024
#define TQ 64
#define TK 64

// ---------------- scratch ----------------
__device__ float g_q[(size_t)NROWS * HQN * DD];
__device__ float g_k[(size_t)NROWS * HKVN * DD];
__device__ float g_v[(size_t)NROWS * HKVN * DD];
__device__ float g_attn[(size_t)NROWS * HQN * DD];

// ---------------- helpers ----------------
__device__ __forceinline__ uint32_t f2tf32(float f) {
    uint32_t u;
    asm("cvt.rna.tf32.f32 %0, %1;" : "=r"(u) : "f"(f));
    return u;
}

__device__ __forceinline__ void mma_tf32(float c[4], const uint32_t a[4], const uint32_t b[2]) {
    asm volatile(
        "mma.sync.aligned.m16n8k8.row.col.f32.tf32.tf32.f32 "
        "{%0,%1,%2,%3}, {%4,%5,%6,%7}, {%8,%9}, {%0,%1,%2,%3};\n"
        : "+f"(c[0]), "+f"(c[1]), "+f"(c[2]), "+f"(c[3])
        : "r"(a[0]), "r"(a[1]), "r"(a[2]), "r"(a[3]), "r"(b[0]), "r"(b[1]));
}

// ---------------- TF32 GEMM (unchanged from round 10) ----------------
#define AS_STRIDE 136
__global__ __launch_bounds__(256) void gemm_tf32_kernel(
    const float* __restrict__ A, const float* __restrict__ B, float* __restrict__ C,
    int M, int N, int K)
{
    __shared__ uint32_t As[16][AS_STRIDE];
    __shared__ uint32_t Bs[16][AS_STRIDE];

    const int tid  = threadIdx.x;
    const int warp = tid >> 5;
    const int lane = tid & 31;
    const int l4   = lane & 3;
    const int l28  = lane >> 2;

    const int m0 = (warp >> 2) * 64;
    const int n0 = (warp & 3) * 32;

    const int row0 = blockIdx.y * 128;
    const int col0 = blockIdx.x * 128;

    float cacc[4][4][4];
#pragma unroll
    for (int mt = 0; mt < 4; mt++)
#pragma unroll
        for (int nt = 0; nt < 4; nt++)
#pragma unroll
            for (int r = 0; r < 4; r++) cacc[mt][nt][r] = 0.0f;

    for (int k0 = 0; k0 < K; k0 += 16) {
#pragma unroll
        for (int i = 0; i < 2; i++) {
            int idx = tid + i * 256;
            int r  = idx >> 2;
            int c4 = (idx & 3) << 2;
            float4 av = *(const float4*)(A + (size_t)(row0 + r) * K + k0 + c4);
            As[c4 + 0][r] = f2tf32(av.x);
            As[c4 + 1][r] = f2tf32(av.y);
            As[c4 + 2][r] = f2tf32(av.z);
            As[c4 + 3][r] = f2tf32(av.w);
        }
#pragma unroll
        for (int i = 0; i < 2; i++) {
            int idx = tid + i * 256;
            int r = idx >> 5;
            int c = (idx & 31) << 2;
            float4 bv = *(const float4*)(B + (size_t)(k0 + r) * N + col0 + c);
            Bs[r][c + 0] = f2tf32(bv.x);
            Bs[r][c + 1] = f2tf32(bv.y);
            Bs[r][c + 2] = f2tf32(bv.z);
            Bs[r][c + 3] = f2tf32(bv.w);
        }
        __syncthreads();

#pragma unroll
        for (int ks = 0; ks < 16; ks += 8) {
            uint32_t bf[4][2];
#pragma unroll
            for (int nt = 0; nt < 4; nt++) {
                int n = n0 + nt * 8 + l28;
                bf[nt][0] = Bs[ks + l4][n];
                bf[nt][1] = Bs[ks + 4 + l4][n];
            }
            uint32_t af[4];
#pragma unroll
            for (int mt = 0; mt < 4; mt++) {
                int m = m0 + mt * 16 + l28;
                af[0] = As[ks + l4][m];
                af[1] = As[ks + l4][m + 8];
                af[2] = As[ks + 4 + l4][m];
                af[3] = As[ks + 4 + l4][m + 8];
#pragma unroll
                for (int nt = 0; nt < 4; nt++)
                    mma_tf32(cacc[mt][nt], af, bf[nt]);
            }
        }
        __syncthreads();
    }

#pragma unroll
    for (int mt = 0; mt < 4; mt++) {
#pragma unroll
        for (int nt = 0; nt < 4; nt++) {
            int row = row0 + m0 + mt * 16 + l28;
            int col = col0 + n0 + nt * 8 + (l4 << 1);
            *(float2*)(C + (size_t)row * N + col)       = make_float2(cacc[mt][nt][0], cacc[mt][nt][1]);
            *(float2*)(C + (size_t)(row + 8) * N + col) = make_float2(cacc[mt][nt][2], cacc[mt][nt][3]);
        }
    }
}

// ---------------- l2norm + RoPE: warp per row ----------------
__global__ __launch_bounds__(256) void norm_rope2_kernel(float* __restrict__ data, int H, int isQ)
{
    const int gw   = blockIdx.x * 8 + (threadIdx.x >> 5);  // global (row*H+h) index
    const int lane = threadIdx.x & 31;
    const int s    = (gw / H) % SS;
    float* ptr = data + (size_t)gw * DD;

    float v0 = ptr[lane];
    float v1 = ptr[lane + 32];
    float v2 = ptr[lane + 64];
    float v3 = ptr[lane + 96];

    float ss = v0 * v0 + v1 * v1 + v2 * v2 + v3 * v3;
#pragma unroll
    for (int off = 16; off > 0; off >>= 1)
        ss += __shfl_xor_sync(0xffffffffu, ss, off);

    float inv = rsqrtf(ss * (1.0f / DD) + 1e-6f);
    v0 *= inv; v1 *= inv; v2 *= inv; v3 *= inv;

    float freq0 = (float)exp(-(double)lane        * (9.210340371976184 / 64.0));
    float freq1 = (float)exp(-(double)(lane + 32) * (9.210340371976184 / 64.0));
    float s0, c0, s1, c1;
    sincosf((float)s * freq0, &s0, &c0);
    sincosf((float)s * freq1, &s1, &c1);

    float o0 = v0 * c0 - v2 * s0;
    float o2 = v2 * c0 + v0 * s0;
    float o1 = v1 * c1 - v3 * s1;
    float o3 = v3 * c1 + v1 * s1;

    if (isQ) {
        float asc = logf(floorf(((float)s + 1.0f) / 8192.0f) + 1.0f) * 0.1f + 1.0f;
        float sc = 0.08838834764831845f * asc;
        o0 *= sc; o1 *= sc; o2 *= sc; o3 *= sc;
    }
    ptr[lane]      = o0;
    ptr[lane + 32] = o1;
    ptr[lane + 64] = o2;
    ptr[lane + 96] = o3;
}

// ---------------- tensor-core flash attention (windowed causal, softcap) ----------------
// grid (SS/64, HQN, BB), 256 threads = 8 warps.
#define QK_STRIDE 132
#define V_STRIDE  136
#define P_STRIDE  68
__global__ __launch_bounds__(256) void attn_tc_kernel()
{
    extern __shared__ uint32_t smu[];
    uint32_t* sQ = smu;                       // 64 x 132 (tf32)
    uint32_t* sK = sQ + 64 * QK_STRIDE;       // 64 x 132 (tf32)
    uint32_t* sV = sK + 64 * QK_STRIDE;       // 64 x 136 (tf32)
    float*    sP = (float*)(sV + 64 * V_STRIDE); // 64 x 68 (logits -> probs, fp32)
    float*    sM = sP + 64 * P_STRIDE;        // 64
    float*    sSum = sM + 64;                 // 64
    float*    sAlpha = sSum + 64;             // 64

    const int b  = blockIdx.z;
    const int h  = blockIdx.y;
    const int q0 = blockIdx.x * TQ;
    const int hk = h / (HQN / HKVN);

    const int tid  = threadIdx.x;
    const int warp = tid >> 5;
    const int lane = tid & 31;
    const int l4   = lane & 3;
    const int l28  = lane >> 2;

    const int wm = warp >> 2;       // 0..1
    const int wn = warp & 3;        // 0..3

    // load Q tile (cvt to tf32)
#pragma unroll
    for (int i = 0; i < 8; i++) {
        int idx = tid + i * 256;                  // 2048 float4
        int r  = idx >> 5;
        int c4 = (idx & 31) << 2;
        float4 qv = *(const float4*)&g_q[(((size_t)(b * SS + q0 + r)) * HQN + h) * DD + c4];
        sQ[r * QK_STRIDE + c4 + 0] = f2tf32(qv.x);
        sQ[r * QK_STRIDE + c4 + 1] = f2tf32(qv.y);
        sQ[r * QK_STRIDE + c4 + 2] = f2tf32(qv.z);
        sQ[r * QK_STRIDE + c4 + 3] = f2tf32(qv.w);
    }
    if (tid < 64) { sM[tid] = -30000.0f; sSum[tid] = 0.0f; }

    // O accumulators: warp tile 32(m) x 32(n): mt(2) x nt(4) frags
    float o[2][4][4];
#pragma unroll
    for (int mt = 0; mt < 2; mt++)
#pragma unroll
        for (int nt = 0; nt < 4; nt++)
#pragma unroll
            for (int r = 0; r < 4; r++) o[mt][nt][r] = 0.0f;

    int jlo = q0 - (WIN - 1); if (jlo < 0) jlo = 0;
    int jt0 = (jlo / TK) * TK;

    for (int jt = jt0; jt <= q0; jt += TK) {
        __syncthreads();   // prev PV consumed sV/sP

        // load K, V tiles (cvt to tf32)
#pragma unroll
        for (int i = 0; i < 8; i++) {
            int idx = tid + i * 256;
            int r  = idx >> 5;
            int c4 = (idx & 31) << 2;
            size_t gbase = (((size_t)(b * SS + jt + r)) * HKVN + hk) * DD + c4;
            float4 kv = *(const float4*)&g_k[gbase];
            sK[r * QK_STRIDE + c4 + 0] = f2tf32(kv.x);
            sK[r * QK_STRIDE + c4 + 1] = f2tf32(kv.y);
            sK[r * QK_STRIDE + c4 + 2] = f2tf32(kv.z);
            sK[r * QK_STRIDE + c4 + 3] = f2tf32(kv.w);
            float4 vv = *(const float4*)&g_v[gbase];
            sV[r * V_STRIDE + c4 + 0] = f2tf32(vv.x);
            sV[r * V_STRIDE + c4 + 1] = f2tf32(vv.y);
            sV[r * V_STRIDE + c4 + 2] = f2tf32(vv.z);
            sV[r * V_STRIDE + c4 + 3] = f2tf32(vv.w);
        }
        __syncthreads();

        // ---- QK^T: warp computes S[32 x 16] at (wm*32, wn*16) ----
        {
            const int sm0 = wm * 32;
            const int sn0 = wn * 16;
            float acc[2][2][4];
#pragma unroll
            for (int mt = 0; mt < 2; mt++)
#pragma unroll
                for (int nt = 0; nt < 2; nt++)
#pragma unroll
                    for (int r = 0; r < 4; r++) acc[mt][nt][r] = 0.0f;

#pragma unroll
            for (int ks = 0; ks < 16; ks++) {
                const int k0 = ks * 8;
                uint32_t bf[2][2];
#pragma unroll
                for (int nt = 0; nt < 2; nt++) {
                    int n = sn0 + nt * 8 + l28;
                    bf[nt][0] = sK[n * QK_STRIDE + k0 + l4];
                    bf[nt][1] = sK[n * QK_STRIDE + k0 + 4 + l4];
                }
#pragma unroll
                for (int mt = 0; mt < 2; mt++) {
                    int m = sm0 + mt * 16 + l28;
                    uint32_t af[4];
                    af[0] = sQ[m * QK_STRIDE + k0 + l4];
                    af[1] = sQ[(m + 8) * QK_STRIDE + k0 + l4];
                    af[2] = sQ[m * QK_STRIDE + k0 + 4 + l4];
                    af[3] = sQ[(m + 8) * QK_STRIDE + k0 + 4 + l4];
#pragma unroll
                    for (int nt = 0; nt < 2; nt++)
                        mma_tf32(acc[mt][nt], af, bf[nt]);
                }
            }

            // softcap + mask -> sP (logits)
#pragma unroll
            for (int mt = 0; mt < 2; mt++) {
#pragma unroll
                for (int nt = 0; nt < 2; nt++) {
#pragma unroll
                    for (int r = 0; r < 4; r++) {
                        int lrow = sm0 + mt * 16 + l28 + ((r >> 1) << 3);
                        int lcol = sn0 + nt * 8 + (l4 << 1) + (r & 1);
                        int i = q0 + lrow;
                        int j = jt + lcol;
                        float lg = 50.0f * tanhf(acc[mt][nt][r] * 0.02f);
                        bool valid = (j <= i) && (i - j < WIN);
                        sP[lrow * P_STRIDE + lcol] = valid ? lg : -30000.0f;
                    }
                }
            }
        }
        __syncthreads();

        // ---- online softmax (thread t owns row t; rotated j to avoid conflicts) ----
        if (tid < 64) {
            float tm = -30000.0f;
            for (int jj = 0; jj < TK; jj++) {
                int j = (jj + tid) & 63;
                tm = fmaxf(tm, sP[tid * P_STRIDE + j]);
            }
            float mo = sM[tid];
            float mn = fmaxf(mo, tm);
            float alpha = __expf(mo - mn);
            float rs = 0.0f;
            for (int jj = 0; jj < TK; jj++) {
                int j = (jj + tid) & 63;
                float lv = sP[tid * P_STRIDE + j];
                float p = (lv > -20000.0f) ? __expf(lv - mn) : 0.0f;
                sP[tid * P_STRIDE + j] = p;
                rs += p;
            }
            sSum[tid] = sSum[tid] * alpha + rs;
            sM[tid] = mn;
            sAlpha[tid] = alpha;
        }
        __syncthreads();

        // ---- PV: warp tile O[32 x 32] at (wm*32, wn*32) ----
        {
            const int om0 = wm * 32;
            const int on0 = wn * 32;
#pragma unroll
            for (int mt = 0; mt < 2; mt++) {
                float a_lo = sAlpha[om0 + mt * 16 + l28];
                float a_hi = sAlpha[om0 + mt * 16 + l28 + 8];
#pragma unroll
                for (int nt = 0; nt < 4; nt++) {
                    o[mt][nt][0] *= a_lo; o[mt][nt][1] *= a_lo;
                    o[mt][nt][2] *= a_hi; o[mt][nt][3] *= a_hi;
                }
            }
#pragma unroll
            for (int ks = 0; ks < 8; ks++) {
                const int jb = ks * 8;
                uint32_t bf[4][2];
#pragma unroll
                for (int nt = 0; nt < 4; nt++) {
                    int n = on0 + nt * 8 + l28;
                    bf[nt][0] = sV[(jb + l4) * V_STRIDE + n];
                    bf[nt][1] = sV[(jb + 4 + l4) * V_STRIDE + n];
                }
#pragma unroll
                for (int mt = 0; mt < 2; mt++) {
                    int m = om0 + mt * 16 + l28;
                    uint32_t af[4];
                    af[0] = f2tf32(sP[m * P_STRIDE + jb + l4]);
                    af[1] = f2tf32(sP[(m + 8) * P_STRIDE + jb + l4]);
                    af[2] = f2tf32(sP[m * P_STRIDE + jb + 4 + l4]);
                    af[3] = f2tf32(sP[(m + 8) * P_STRIDE + jb + 4 + l4]);
#pragma unroll
                    for (int nt = 0; nt < 4; nt++)
                        mma_tf32(o[mt][nt], af, bf[nt]);
                }
            }
        }
    }

    // epilogue: normalize and store
    {
        const int om0 = wm * 32;
        const int on0 = wn * 32;
#pragma unroll
        for (int mt = 0; mt < 2; mt++) {
            int rlo = om0 + mt * 16 + l28;
            float inv_lo = 1.0f / sSum[rlo];
            float inv_hi = 1.0f / sSum[rlo + 8];
#pragma unroll
            for (int nt = 0; nt < 4; nt++) {
                int col = on0 + nt * 8 + (l4 << 1);
                size_t base_lo = (((size_t)(b * SS + q0 + rlo)) * HQN + h) * DD + col;
                size_t base_hi = (((size_t)(b * SS + q0 + rlo + 8)) * HQN + h) * DD + col;
                *(float2*)&g_attn[base_lo] = make_float2(o[mt][nt][0] * inv_lo, o[mt][nt][1] * inv_lo);
                *(float2*)&g_attn[base_hi] = make_float2(o[mt][nt][2] * inv_hi, o[mt][nt][3] * inv_hi);
            }
        }
    }
}

// ---------------- launch ----------------
extern "C" void kernel_launch(void* const* d_in, const int* in_sizes, int n_in,
                              void* d_out, int out_size)
{
    const float* x  = (const float*)d_in[0];
    const float* Wq = (const float*)d_in[1];
    const float* Wk = (const float*)d_in[2];
    const float* Wv = (const float*)d_in[3];
    const float* Wo = (const float*)d_in[4];
    float* out = (float*)d_out;

    float *q, *k, *v, *attn;
    cudaGetSymbolAddress((void**)&q,    g_q);
    cudaGetSymbolAddress((void**)&k,    g_k);
    cudaGetSymbolAddress((void**)&v,    g_v);
    cudaGetSymbolAddress((void**)&attn, g_attn);

    // QKV projections (tf32 tensor cores)
    gemm_tf32_kernel<<<dim3(HQN * DD / 128, NROWS / 128), 256>>>(x, Wq, q, NROWS, HQN * DD, EE);
    gemm_tf32_kernel<<<dim3(HKVN * DD / 128, NROWS / 128), 256>>>(x, Wk, k, NROWS, HKVN * DD, EE);
    gemm_tf32_kernel<<<dim3(HKVN * DD / 128, NROWS / 128), 256>>>(x, Wv, v, NROWS, HKVN * DD, EE);

    // l2norm + rope (warp-per-row)
    norm_rope2_kernel<<<NROWS * HQN / 8, 256>>>(q, HQN, 1);
    norm_rope2_kernel<<<NROWS * HKVN / 8, 256>>>(k, HKVN, 0);

    // attention (tensor cores)
    const int att_smem = (64 * QK_STRIDE * 2 + 64 * V_STRIDE) * 4 + (64 * P_STRIDE + 3 * 64) * 4;
    cudaFuncSetAttribute(attn_tc_kernel, cudaFuncAttributeMaxDynamicSharedMemorySize, att_smem);
    attn_tc_kernel<<<dim3(SS / TQ, HQN, BB), 256, att_smem>>>();

    // output projection (tf32 tensor cores)
    gemm_tf32_kernel<<<dim3(EE / 128, NROWS / 128), 256>>>(attn, Wo, out, NROWS, EE, HQN * DD);
}

// round 12
// speedup vs baseline: 3.2209x; 1.4516x over previous
#include <cuda_runtime.h>
#include <math.h>
#include <stdint.h>

#define BB 2
#define SS 2048
#define EE 4096
#define HQN 32
#define HKVN 8
#define DD 128
#define NROWS (BB*SS)      // 4096
#define WIN 1024
#define TQ 64
#define TK 64

// ---------------- scratch ----------------
__device__ float g_q[(size_t)NROWS * HQN * DD];
__device__ float g_k[(size_t)NROWS * HKVN * DD];
__device__ float g_v[(size_t)NROWS * HKVN * DD];
__device__ float g_attn[(size_t)NROWS * HQN * DD];
// tf32 copies for pipelined GEMMs
__device__ uint32_t g_xt[(size_t)NROWS * EE];
__device__ uint32_t g_wqt[(size_t)EE * HQN * DD];
__device__ uint32_t g_wkt[(size_t)EE * HKVN * DD];
__device__ uint32_t g_wvt[(size_t)EE * HKVN * DD];
__device__ uint32_t g_wot[(size_t)HQN * DD * EE];
__device__ uint32_t g_attnt[(size_t)NROWS * HQN * DD];

// ---------------- helpers ----------------
__device__ __forceinline__ uint32_t f2tf32(float f) {
    uint32_t u;
    asm("cvt.rna.tf32.f32 %0, %1;" : "=r"(u) : "f"(f));
    return u;
}

__device__ __forceinline__ void mma_tf32(float c[4], const uint32_t a[4], const uint32_t b[2]) {
    asm volatile(
        "mma.sync.aligned.m16n8k8.row.col.f32.tf32.tf32.f32 "
        "{%0,%1,%2,%3}, {%4,%5,%6,%7}, {%8,%9}, {%0,%1,%2,%3};\n"
        : "+f"(c[0]), "+f"(c[1]), "+f"(c[2]), "+f"(c[3])
        : "r"(a[0]), "r"(a[1]), "r"(a[2]), "r"(a[3]), "r"(b[0]), "r"(b[1]));
}

__device__ __forceinline__ void cp16(void* sdst, const void* gsrc) {
    uint32_t sa = (uint32_t)__cvta_generic_to_shared(sdst);
    asm volatile("cp.async.cg.shared.global [%0], [%1], 16;\n" :: "r"(sa), "l"(gsrc));
}

// ---------------- fp32 -> tf32 conversion (4 elems/thread) ----------------
__global__ __launch_bounds__(256) void cvt_tf32_kernel(const float* __restrict__ in,
                                                       uint32_t* __restrict__ out)
{
    size_t i = ((size_t)blockIdx.x * 256 + threadIdx.x) * 4;
    float4 v = *(const float4*)(in + i);
    uint4 u;
    u.x = f2tf32(v.x); u.y = f2tf32(v.y); u.z = f2tf32(v.z); u.w = f2tf32(v.w);
    *(uint4*)(out + i) = u;
}

// ---------------- pipelined TF32 GEMM: C[MxN] = A*B, operands pre-converted ----------------
// 128x128 tile, K-chunk 32, 2-stage cp.async double buffer, 256 thr (8 warps), warp 64x32.
#define A_ST 36      // A smem row stride [m][k]: (4m + k) banks all distinct
#define B_ST 136     // B smem row stride [k][n]: (8k + n) banks all distinct
#define A_STAGE (128 * A_ST)
#define B_STAGE (32 * B_ST)

__device__ __forceinline__ void gemm_load_stage(
    const uint32_t* __restrict__ A, const uint32_t* __restrict__ B,
    uint32_t* __restrict__ as, uint32_t* __restrict__ bs,
    int row0, int col0, int k0, int K, int N, int tid)
{
#pragma unroll
    for (int it = 0; it < 4; it++) {
        int idx = tid + it * 256;                // 1024 chunks: 128 rows x 8
        int r  = idx >> 3;
        int ch = (idx & 7) << 2;
        cp16(as + r * A_ST + ch, A + (size_t)(row0 + r) * K + k0 + ch);
    }
#pragma unroll
    for (int it = 0; it < 4; it++) {
        int idx = tid + it * 256;                // 1024 chunks: 32 rows x 32
        int r  = idx >> 5;
        int ch = (idx & 31) << 2;
        cp16(bs + r * B_ST + ch, B + (size_t)(k0 + r) * N + col0 + ch);
    }
    asm volatile("cp.async.commit_group;\n");
}

__global__ __launch_bounds__(256, 2) void gemm_tf32p_kernel(
    const uint32_t* __restrict__ A, const uint32_t* __restrict__ B, float* __restrict__ C,
    int M, int N, int K)
{
    extern __shared__ uint32_t sh[];
    uint32_t* As = sh;                     // 2 stages [128][A_ST]
    uint32_t* Bs = sh + 2 * A_STAGE;       // 2 stages [32][B_ST]

    const int tid  = threadIdx.x;
    const int warp = tid >> 5;
    const int lane = tid & 31;
    const int l4   = lane & 3;
    const int l28  = lane >> 2;

    const int m0 = (warp >> 2) * 64;
    const int n0 = (warp & 3) * 32;
    const int row0 = blockIdx.y * 128;
    const int col0 = blockIdx.x * 128;

    float cacc[4][4][4];
#pragma unroll
    for (int mt = 0; mt < 4; mt++)
#pragma unroll
        for (int nt = 0; nt < 4; nt++)
#pragma unroll
            for (int r = 0; r < 4; r++) cacc[mt][nt][r] = 0.0f;

    const int T = K >> 5;                  // K / 32
    gemm_load_stage(A, B, As, Bs, row0, col0, 0, K, N, tid);

    for (int kt = 0; kt < T; kt++) {
        if (kt + 1 < T) {
            gemm_load_stage(A, B, As + ((kt + 1) & 1) * A_STAGE, Bs + ((kt + 1) & 1) * B_STAGE,
                            row0, col0, (kt + 1) << 5, K, N, tid);
            asm volatile("cp.async.wait_group 1;\n");
        } else {
            asm volatile("cp.async.wait_group 0;\n");
        }
        __syncthreads();

        const uint32_t* as = As + (kt & 1) * A_STAGE;
        const uint32_t* bs = Bs + (kt & 1) * B_STAGE;

#pragma unroll
        for (int ks = 0; ks < 32; ks += 8) {
            uint32_t bf[4][2];
#pragma unroll
            for (int nt = 0; nt < 4; nt++) {
                int n = n0 + nt * 8 + l28;
                bf[nt][0] = bs[(ks + l4) * B_ST + n];
                bf[nt][1] = bs[(ks + 4 + l4) * B_ST + n];
            }
#pragma unroll
            for (int mt = 0; mt < 4; mt++) {
                int m = m0 + mt * 16 + l28;
                uint32_t af[4];
                af[0] = as[m * A_ST + ks + l4];
                af[1] = as[(m + 8) * A_ST + ks + l4];
                af[2] = as[m * A_ST + ks + 4 + l4];
                af[3] = as[(m + 8) * A_ST + ks + 4 + l4];
#pragma unroll
                for (int nt = 0; nt < 4; nt++)
                    mma_tf32(cacc[mt][nt], af, bf[nt]);
            }
        }
        __syncthreads();
    }

#pragma unroll
    for (int mt = 0; mt < 4; mt++) {
#pragma unroll
        for (int nt = 0; nt < 4; nt++) {
            int row = row0 + m0 + mt * 16 + l28;
            int col = col0 + n0 + nt * 8 + (l4 << 1);
            *(float2*)(C + (size_t)row * N + col)       = make_float2(cacc[mt][nt][0], cacc[mt][nt][1]);
            *(float2*)(C + (size_t)(row + 8) * N + col) = make_float2(cacc[mt][nt][2], cacc[mt][nt][3]);
        }
    }
}

// ---------------- l2norm + RoPE: warp per row ----------------
__global__ __launch_bounds__(256) void norm_rope2_kernel(float* __restrict__ data, int H, int isQ)
{
    const int gw   = blockIdx.x * 8 + (threadIdx.x >> 5);
    const int lane = threadIdx.x & 31;
    const int s    = (gw / H) % SS;
    float* ptr = data + (size_t)gw * DD;

    float v0 = ptr[lane];
    float v1 = ptr[lane + 32];
    float v2 = ptr[lane + 64];
    float v3 = ptr[lane + 96];

    float ss = v0 * v0 + v1 * v1 + v2 * v2 + v3 * v3;
#pragma unroll
    for (int off = 16; off > 0; off >>= 1)
        ss += __shfl_xor_sync(0xffffffffu, ss, off);

    float inv = rsqrtf(ss * (1.0f / DD) + 1e-6f);
    v0 *= inv; v1 *= inv; v2 *= inv; v3 *= inv;

    float freq0 = (float)exp(-(double)lane        * (9.210340371976184 / 64.0));
    float freq1 = (float)exp(-(double)(lane + 32) * (9.210340371976184 / 64.0));
    float s0, c0, s1, c1;
    sincosf((float)s * freq0, &s0, &c0);
    sincosf((float)s * freq1, &s1, &c1);

    float o0 = v0 * c0 - v2 * s0;
    float o2 = v2 * c0 + v0 * s0;
    float o1 = v1 * c1 - v3 * s1;
    float o3 = v3 * c1 + v1 * s1;

    if (isQ) {
        float asc = logf(floorf(((float)s + 1.0f) / 8192.0f) + 1.0f) * 0.1f + 1.0f;
        float sc = 0.08838834764831845f * asc;
        o0 *= sc; o1 *= sc; o2 *= sc; o3 *= sc;
    }
    ptr[lane]      = o0;
    ptr[lane + 32] = o1;
    ptr[lane + 64] = o2;
    ptr[lane + 96] = o3;
}

// ---------------- tensor-core flash attention (unchanged from round 11) ----------------
#define QK_STRIDE 132
#define V_STRIDE  136
#define P_STRIDE  68
__global__ __launch_bounds__(256) void attn_tc_kernel()
{
    extern __shared__ uint32_t smu[];
    uint32_t* sQ = smu;
    uint32_t* sK = sQ + 64 * QK_STRIDE;
    uint32_t* sV = sK + 64 * QK_STRIDE;
    float*    sP = (float*)(sV + 64 * V_STRIDE);
    float*    sM = sP + 64 * P_STRIDE;
    float*    sSum = sM + 64;
    float*    sAlpha = sSum + 64;

    const int b  = blockIdx.z;
    const int h  = blockIdx.y;
    const int q0 = blockIdx.x * TQ;
    const int hk = h / (HQN / HKVN);

    const int tid  = threadIdx.x;
    const int warp = tid >> 5;
    const int lane = tid & 31;
    const int l4   = lane & 3;
    const int l28  = lane >> 2;

    const int wm = warp >> 2;
    const int wn = warp & 3;

#pragma unroll
    for (int i = 0; i < 8; i++) {
        int idx = tid + i * 256;
        int r  = idx >> 5;
        int c4 = (idx & 31) << 2;
        float4 qv = *(const float4*)&g_q[(((size_t)(b * SS + q0 + r)) * HQN + h) * DD + c4];
        sQ[r * QK_STRIDE + c4 + 0] = f2tf32(qv.x);
        sQ[r * QK_STRIDE + c4 + 1] = f2tf32(qv.y);
        sQ[r * QK_STRIDE + c4 + 2] = f2tf32(qv.z);
        sQ[r * QK_STRIDE + c4 + 3] = f2tf32(qv.w);
    }
    if (tid < 64) { sM[tid] = -30000.0f; sSum[tid] = 0.0f; }

    float o[2][4][4];
#pragma unroll
    for (int mt = 0; mt < 2; mt++)
#pragma unroll
        for (int nt = 0; nt < 4; nt++)
#pragma unroll
            for (int r = 0; r < 4; r++) o[mt][nt][r] = 0.0f;

    int jlo = q0 - (WIN - 1); if (jlo < 0) jlo = 0;
    int jt0 = (jlo / TK) * TK;

    for (int jt = jt0; jt <= q0; jt += TK) {
        __syncthreads();

#pragma unroll
        for (int i = 0; i < 8; i++) {
            int idx = tid + i * 256;
            int r  = idx >> 5;
            int c4 = (idx & 31) << 2;
            size_t gbase = (((size_t)(b * SS + jt + r)) * HKVN + hk) * DD + c4;
            float4 kv = *(const float4*)&g_k[gbase];
            sK[r * QK_STRIDE + c4 + 0] = f2tf32(kv.x);
            sK[r * QK_STRIDE + c4 + 1] = f2tf32(kv.y);
            sK[r * QK_STRIDE + c4 + 2] = f2tf32(kv.z);
            sK[r * QK_STRIDE + c4 + 3] = f2tf32(kv.w);
            float4 vv = *(const float4*)&g_v[gbase];
            sV[r * V_STRIDE + c4 + 0] = f2tf32(vv.x);
            sV[r * V_STRIDE + c4 + 1] = f2tf32(vv.y);
            sV[r * V_STRIDE + c4 + 2] = f2tf32(vv.z);
            sV[r * V_STRIDE + c4 + 3] = f2tf32(vv.w);
        }
        __syncthreads();

        {
            const int sm0 = wm * 32;
            const int sn0 = wn * 16;
            float acc[2][2][4];
#pragma unroll
            for (int mt = 0; mt < 2; mt++)
#pragma unroll
                for (int nt = 0; nt < 2; nt++)
#pragma unroll
                    for (int r = 0; r < 4; r++) acc[mt][nt][r] = 0.0f;

#pragma unroll
            for (int ks = 0; ks < 16; ks++) {
                const int k0 = ks * 8;
                uint32_t bf[2][2];
#pragma unroll
                for (int nt = 0; nt < 2; nt++) {
                    int n = sn0 + nt * 8 + l28;
                    bf[nt][0] = sK[n * QK_STRIDE + k0 + l4];
                    bf[nt][1] = sK[n * QK_STRIDE + k0 + 4 + l4];
                }
#pragma unroll
                for (int mt = 0; mt < 2; mt++) {
                    int m = sm0 + mt * 16 + l28;
                    uint32_t af[4];
                    af[0] = sQ[m * QK_STRIDE + k0 + l4];
                    af[1] = sQ[(m + 8) * QK_STRIDE + k0 + l4];
                    af[2] = sQ[m * QK_STRIDE + k0 + 4 + l4];
                    af[3] = sQ[(m + 8) * QK_STRIDE + k0 + 4 + l4];
#pragma unroll
                    for (int nt = 0; nt < 2; nt++)
                        mma_tf32(acc[mt][nt], af, bf[nt]);
                }
            }

#pragma unroll
            for (int mt = 0; mt < 2; mt++) {
#pragma unroll
                for (int nt = 0; nt < 2; nt++) {
#pragma unroll
                    for (int r = 0; r < 4; r++) {
                        int lrow = sm0 + mt * 16 + l28 + ((r >> 1) << 3);
                        int lcol = sn0 + nt * 8 + (l4 << 1) + (r & 1);
                        int i = q0 + lrow;
                        int j = jt + lcol;
                        float lg = 50.0f * tanhf(acc[mt][nt][r] * 0.02f);
                        bool valid = (j <= i) && (i - j < WIN);
                        sP[lrow * P_STRIDE + lcol] = valid ? lg : -30000.0f;
                    }
                }
            }
        }
        __syncthreads();

        if (tid < 64) {
            float tm = -30000.0f;
            for (int jj = 0; jj < TK; jj++) {
                int j = (jj + tid) & 63;
                tm = fmaxf(tm, sP[tid * P_STRIDE + j]);
            }
            float mo = sM[tid];
            float mn = fmaxf(mo, tm);
            float alpha = __expf(mo - mn);
            float rs = 0.0f;
            for (int jj = 0; jj < TK; jj++) {
                int j = (jj + tid) & 63;
                float lv = sP[tid * P_STRIDE + j];
                float p = (lv > -20000.0f) ? __expf(lv - mn) : 0.0f;
                sP[tid * P_STRIDE + j] = p;
                rs += p;
            }
            sSum[tid] = sSum[tid] * alpha + rs;
            sM[tid] = mn;
            sAlpha[tid] = alpha;
        }
        __syncthreads();

        {
            const int om0 = wm * 32;
            const int on0 = wn * 32;
#pragma unroll
            for (int mt = 0; mt < 2; mt++) {
                float a_lo = sAlpha[om0 + mt * 16 + l28];
                float a_hi = sAlpha[om0 + mt * 16 + l28 + 8];
#pragma unroll
                for (int nt = 0; nt < 4; nt++) {
                    o[mt][nt][0] *= a_lo; o[mt][nt][1] *= a_lo;
                    o[mt][nt][2] *= a_hi; o[mt][nt][3] *= a_hi;
                }
            }
#pragma unroll
            for (int ks = 0; ks < 8; ks++) {
                const int jb = ks * 8;
                uint32_t bf[4][2];
#pragma unroll
                for (int nt = 0; nt < 4; nt++) {
                    int n = on0 + nt * 8 + l28;
                    bf[nt][0] = sV[(jb + l4) * V_STRIDE + n];
                    bf[nt][1] = sV[(jb + 4 + l4) * V_STRIDE + n];
                }
#pragma unroll
                for (int mt = 0; mt < 2; mt++) {
                    int m = om0 + mt * 16 + l28;
                    uint32_t af[4];
                    af[0] = f2tf32(sP[m * P_STRIDE + jb + l4]);
                    af[1] = f2tf32(sP[(m + 8) * P_STRIDE + jb + l4]);
                    af[2] = f2tf32(sP[m * P_STRIDE + jb + 4 + l4]);
                    af[3] = f2tf32(sP[(m + 8) * P_STRIDE + jb + 4 + l4]);
#pragma unroll
                    for (int nt = 0; nt < 4; nt++)
                        mma_tf32(o[mt][nt], af, bf[nt]);
                }
            }
        }
    }

    {
        const int om0 = wm * 32;
        const int on0 = wn * 32;
#pragma unroll
        for (int mt = 0; mt < 2; mt++) {
            int rlo = om0 + mt * 16 + l28;
            float inv_lo = 1.0f / sSum[rlo];
            float inv_hi = 1.0f / sSum[rlo + 8];
#pragma unroll
            for (int nt = 0; nt < 4; nt++) {
                int col = on0 + nt * 8 + (l4 << 1);
                size_t base_lo = (((size_t)(b * SS + q0 + rlo)) * HQN + h) * DD + col;
                size_t base_hi = (((size_t)(b * SS + q0 + rlo + 8)) * HQN + h) * DD + col;
                *(float2*)&g_attn[base_lo] = make_float2(o[mt][nt][0] * inv_lo, o[mt][nt][1] * inv_lo);
                *(float2*)&g_attn[base_hi] = make_float2(o[mt][nt][2] * inv_hi, o[mt][nt][3] * inv_hi);
            }
        }
    }
}

// ---------------- launch ----------------
extern "C" void kernel_launch(void* const* d_in, const int* in_sizes, int n_in,
                              void* d_out, int out_size)
{
    const float* x  = (const float*)d_in[0];
    const float* Wq = (const float*)d_in[1];
    const float* Wk = (const float*)d_in[2];
    const float* Wv = (const float*)d_in[3];
    const float* Wo = (const float*)d_in[4];
    float* out = (float*)d_out;

    float *q, *k, *v, *attn;
    uint32_t *xt, *wqt, *wkt, *wvt, *wot, *attnt;
    cudaGetSymbolAddress((void**)&q,    g_q);
    cudaGetSymbolAddress((void**)&k,    g_k);
    cudaGetSymbolAddress((void**)&v,    g_v);
    cudaGetSymbolAddress((void**)&attn, g_attn);
    cudaGetSymbolAddress((void**)&xt,   g_xt);
    cudaGetSymbolAddress((void**)&wqt,  g_wqt);
    cudaGetSymbolAddress((void**)&wkt,  g_wkt);
    cudaGetSymbolAddress((void**)&wvt,  g_wvt);
    cudaGetSymbolAddress((void**)&wot,  g_wot);
    cudaGetSymbolAddress((void**)&attnt,g_attnt);

    const size_t NBIG = (size_t)NROWS * EE;            // 16.7M
    const size_t NSML = (size_t)EE * HKVN * DD;        // 4.2M

    // pre-convert operands to tf32
    cvt_tf32_kernel<<<(int)(NBIG / 1024), 256>>>(x,  xt);
    cvt_tf32_kernel<<<(int)(NBIG / 1024), 256>>>(Wq, wqt);
    cvt_tf32_kernel<<<(int)(NSML / 1024), 256>>>(Wk, wkt);
    cvt_tf32_kernel<<<(int)(NSML / 1024), 256>>>(Wv, wvt);
    cvt_tf32_kernel<<<(int)(NBIG / 1024), 256>>>(Wo, wot);

    const int gemm_smem = (2 * A_STAGE + 2 * B_STAGE) * 4;   // 71680
    cudaFuncSetAttribute(gemm_tf32p_kernel, cudaFuncAttributeMaxDynamicSharedMemorySize, gemm_smem);

    // QKV projections
    gemm_tf32p_kernel<<<dim3(HQN * DD / 128, NROWS / 128), 256, gemm_smem>>>(xt, wqt, q, NROWS, HQN * DD, EE);
    gemm_tf32p_kernel<<<dim3(HKVN * DD / 128, NROWS / 128), 256, gemm_smem>>>(xt, wkt, k, NROWS, HKVN * DD, EE);
    gemm_tf32p_kernel<<<dim3(HKVN * DD / 128, NROWS / 128), 256, gemm_smem>>>(xt, wvt, v, NROWS, HKVN * DD, EE);

    // l2norm + rope
    norm_rope2_kernel<<<NROWS * HQN / 8, 256>>>(q, HQN, 1);
    norm_rope2_kernel<<<NROWS * HKVN / 8, 256>>>(k, HKVN, 0);

    // attention (tensor cores)
    const int att_smem = (64 * QK_STRIDE * 2 + 64 * V_STRIDE) * 4 + (64 * P_STRIDE + 3 * 64) * 4;
    cudaFuncSetAttribute(attn_tc_kernel, cudaFuncAttributeMaxDynamicSharedMemorySize, att_smem);
    attn_tc_kernel<<<dim3(SS / TQ, HQN, BB), 256, att_smem>>>();

    // output projection
    cvt_tf32_kernel<<<(int)(NBIG / 1024), 256>>>(attn, attnt);
    gemm_tf32p_kernel<<<dim3(EE / 128, NROWS / 128), 256, gemm_smem>>>(attnt, wot, out, NROWS, EE, HQN * DD);
}